// round 9
// baseline (speedup 1.0000x reference)
#include <cuda_runtime.h>
#include <cstdint>

// MixtureCrossattention, per batch b: C = [e1|e2] (16x576), e = patch_embed(x).
// For query col q (0..575): w_p = lam(p,q) * softmax-term of C[:,q]·C[:,p];
//   q >= 288 -> x3 output col q-288 (lam .7 on e1 keys / .3 on e2)
//   q <  288 -> x4 output col q     (lam .3 on e1 keys / .7 on e2)
// (reference's batch-0 block-transpose is a no-op: e2^T e2 block is symmetric)
//
// One CTA per batch, 192 threads, THREE queries per thread (t, t+192, t+384):
// each 64B key broadcast from smem feeds 48 warp-fma2 instead of 16, moving the
// kernel off the LDS/RF broadcast-return bound onto the fma pipe.
// lambda folded into exponent bias: w = 2^(s*log2e + log2 lam) = lam * e^s.

#define LOG2E   1.4426950408889634f
#define LOG2_07 (-0.5145731728297583f)
#define LOG2_03 (-1.7369655941662063f)

typedef unsigned long long ull;

__device__ __forceinline__ ull pack2(float lo, float hi) {
    ull r; asm("mov.b64 %0, {%1, %2};" : "=l"(r) : "f"(lo), "f"(hi)); return r;
}
__device__ __forceinline__ void unpack2(ull v, float &lo, float &hi) {
    asm("mov.b64 {%0, %1}, %2;" : "=f"(lo), "=f"(hi) : "l"(v));
}
__device__ __forceinline__ ull fma2(ull a, ull b, ull c) {
    ull d; asm("fma.rn.f32x2 %0, %1, %2, %3;" : "=l"(d) : "l"(a), "l"(b), "l"(c)); return d;
}
__device__ __forceinline__ float ex2a(float x) {
    float y; asm("ex2.approx.f32 %0, %1;" : "=f"(y) : "f"(x)); return y;
}

__global__ __launch_bounds__(192, 2)
void mixca_kernel(const float* __restrict__ x1,
                  const float* __restrict__ x2,
                  float* __restrict__ out)
{
    // phase 1: sB[j*16 + i] = C[i][j]   (576 keys x 16 dims, 36.9 KB)
    // phase 2: sB[q*17 + i] = output staging (576 x 17, 39.2 KB)
    __shared__ __align__(16) float sB[576 * 17];

    const int b = blockIdx.x;
    const int t = threadIdx.x;   // 0..191

    // ---- Load + patch-embed both inputs ----
    {
        const float* src0 = x1 + (size_t)b * 4608;
        const float* src1 = x2 + (size_t)b * 4608;
        #pragma unroll
        for (int e = 0; e < 2; e++) {
            const float* src = (e == 0) ? src0 : src1;
            #pragma unroll
            for (int k = 0; k < 24; k++) {
                int g = t + k * 192;           // linear idx into [32][12][12]
                float v = src[g];
                int c   = g / 144;
                int rem = g - c * 144;
                int r   = rem / 12;
                int s   = rem - r * 12;
                int h = r / 3, p1 = r - h * 3;
                int w = s / 3, p2 = s - w * 3;
                int i = h * 4 + w;                        // 0..15
                int j = (p1 * 3 + p2) * 32 + c + e * 288; // 0..575
                sB[j * 16 + i] = v;
            }
        }
    }
    __syncthreads();

    // ---- Three query vectors: cols t, t+192, t+384; dims packed, *log2(e) ----
    ull qv[3][8];
    float bseg0[3], bseg1[3];
    #pragma unroll
    for (int j = 0; j < 3; j++) {
        const int q = t + 192 * j;
        const float4* qp = reinterpret_cast<const float4*>(&sB[q * 16]);
        #pragma unroll
        for (int u = 0; u < 4; u++) {
            float4 qq = qp[u];
            qv[j][2 * u]     = pack2(qq.x * LOG2E, qq.y * LOG2E);
            qv[j][2 * u + 1] = pack2(qq.z * LOG2E, qq.w * LOG2E);
        }
        bseg0[j] = (q >= 288) ? LOG2_07 : LOG2_03;  // keys 0..287 (e1)
        bseg1[j] = (q >= 288) ? LOG2_03 : LOG2_07;  // keys 288..575 (e2)
    }

    ull acc[3][8];
    #pragma unroll
    for (int j = 0; j < 3; j++)
        #pragma unroll
        for (int u = 0; u < 8; u++) acc[j][u] = 0ull;
    float sw[3][2] = {{0.f,0.f},{0.f,0.f},{0.f,0.f}};

    #pragma unroll 1
    for (int seg = 0; seg < 2; seg++) {
        ull bias[3];
        #pragma unroll
        for (int j = 0; j < 3; j++)
            bias[j] = pack2(seg ? bseg1[j] : bseg0[j], 0.0f);
        float s0 = 0.f, s1 = 0.f, s2 = 0.f;
        const ulonglong2* base =
            reinterpret_cast<const ulonglong2*>(&sB[seg * 288 * 16]);

        #pragma unroll 1
        for (int c = 0; c < 288; c++) {
            // one key column: 16 dims, loaded once, feeds 3 queries
            ulonglong2 k0 = base[c * 4 + 0];
            ulonglong2 k1 = base[c * 4 + 1];
            ulonglong2 k2 = base[c * 4 + 2];
            ulonglong2 k3 = base[c * 4 + 3];

            ull sc0 = fma2(qv[0][0], k0.x, bias[0]);
            ull sc1 = fma2(qv[1][0], k0.x, bias[1]);
            ull sc2 = fma2(qv[2][0], k0.x, bias[2]);
            sc0 = fma2(qv[0][1], k0.y, sc0);
            sc1 = fma2(qv[1][1], k0.y, sc1);
            sc2 = fma2(qv[2][1], k0.y, sc2);
            sc0 = fma2(qv[0][2], k1.x, sc0);
            sc1 = fma2(qv[1][2], k1.x, sc1);
            sc2 = fma2(qv[2][2], k1.x, sc2);
            sc0 = fma2(qv[0][3], k1.y, sc0);
            sc1 = fma2(qv[1][3], k1.y, sc1);
            sc2 = fma2(qv[2][3], k1.y, sc2);
            sc0 = fma2(qv[0][4], k2.x, sc0);
            sc1 = fma2(qv[1][4], k2.x, sc1);
            sc2 = fma2(qv[2][4], k2.x, sc2);
            sc0 = fma2(qv[0][5], k2.y, sc0);
            sc1 = fma2(qv[1][5], k2.y, sc1);
            sc2 = fma2(qv[2][5], k2.y, sc2);
            sc0 = fma2(qv[0][6], k3.x, sc0);
            sc1 = fma2(qv[1][6], k3.x, sc1);
            sc2 = fma2(qv[2][6], k3.x, sc2);
            sc0 = fma2(qv[0][7], k3.y, sc0);
            sc1 = fma2(qv[1][7], k3.y, sc1);
            sc2 = fma2(qv[2][7], k3.y, sc2);

            float lo, hi;
            unpack2(sc0, lo, hi);  float w0 = ex2a(lo + hi);
            unpack2(sc1, lo, hi);  float w1 = ex2a(lo + hi);
            unpack2(sc2, lo, hi);  float w2 = ex2a(lo + hi);
            s0 += w0;  s1 += w1;  s2 += w2;
            ull w0p = pack2(w0, w0);
            ull w1p = pack2(w1, w1);
            ull w2p = pack2(w2, w2);

            acc[0][0] = fma2(w0p, k0.x, acc[0][0]);
            acc[1][0] = fma2(w1p, k0.x, acc[1][0]);
            acc[2][0] = fma2(w2p, k0.x, acc[2][0]);
            acc[0][1] = fma2(w0p, k0.y, acc[0][1]);
            acc[1][1] = fma2(w1p, k0.y, acc[1][1]);
            acc[2][1] = fma2(w2p, k0.y, acc[2][1]);
            acc[0][2] = fma2(w0p, k1.x, acc[0][2]);
            acc[1][2] = fma2(w1p, k1.x, acc[1][2]);
            acc[2][2] = fma2(w2p, k1.x, acc[2][2]);
            acc[0][3] = fma2(w0p, k1.y, acc[0][3]);
            acc[1][3] = fma2(w1p, k1.y, acc[1][3]);
            acc[2][3] = fma2(w2p, k1.y, acc[2][3]);
            acc[0][4] = fma2(w0p, k2.x, acc[0][4]);
            acc[1][4] = fma2(w1p, k2.x, acc[1][4]);
            acc[2][4] = fma2(w2p, k2.x, acc[2][4]);
            acc[0][5] = fma2(w0p, k2.y, acc[0][5]);
            acc[1][5] = fma2(w1p, k2.y, acc[1][5]);
            acc[2][5] = fma2(w2p, k2.y, acc[2][5]);
            acc[0][6] = fma2(w0p, k3.x, acc[0][6]);
            acc[1][6] = fma2(w1p, k3.x, acc[1][6]);
            acc[2][6] = fma2(w2p, k3.x, acc[2][6]);
            acc[0][7] = fma2(w0p, k3.y, acc[0][7]);
            acc[1][7] = fma2(w1p, k3.y, acc[1][7]);
            acc[2][7] = fma2(w2p, k3.y, acc[2][7]);
        }
        sw[0][seg] = s0;  sw[1][seg] = s1;  sw[2][seg] = s2;
    }

    // denominators: Z = sw_seg0/lam_seg0 + sw_seg1/lam_seg1
    float inv[3];
    #pragma unroll
    for (int j = 0; j < 3; j++) {
        const int q = t + 192 * j;
        const float iA = (q >= 288) ? (1.0f / 0.7f) : (1.0f / 0.3f);
        const float iB = (q >= 288) ? (1.0f / 0.3f) : (1.0f / 0.7f);
        inv[j] = 1.0f / (sw[j][0] * iA + sw[j][1] * iB);
    }

    __syncthreads();          // keys no longer needed; reuse sB as staging
    #pragma unroll
    for (int j = 0; j < 3; j++) {
        const int q = t + 192 * j;
        #pragma unroll
        for (int u = 0; u < 8; u++) {
            float lo, hi;
            unpack2(acc[j][u], lo, hi);
            sB[q * 17 + 2 * u]     = lo * inv[j];
            sB[q * 17 + 2 * u + 1] = hi * inv[j];
        }
    }
    __syncthreads();

    // ---- Coalesced un-patch stores: x3 block (queries 288+tt), then x4 (tt) ----
    #pragma unroll
    for (int half = 0; half < 2; half++) {
        float* dst = out + ((size_t)half * 512 + (size_t)b) * 4608;
        #pragma unroll
        for (int k = 0; k < 24; k++) {
            int g = t + k * 192;
            int c   = g / 144;
            int rem = g - c * 144;
            int r   = rem / 12;
            int s   = rem - r * 12;
            int h = r / 3, p1 = r - h * 3;
            int w = s / 3, p2 = s - w * 3;
            int i  = h * 4 + w;
            int tt = (p1 * 3 + p2) * 32 + c;
            int q  = (half == 0) ? (288 + tt) : tt;
            dst[g] = sB[q * 17 + i];
        }
    }
}

extern "C" void kernel_launch(void* const* d_in, const int* in_sizes, int n_in,
                              void* d_out, int out_size)
{
    const float* x1 = (const float*)d_in[0];
    const float* x2 = (const float*)d_in[1];
    float* out = (float*)d_out;
    mixca_kernel<<<512, 192>>>(x1, x2, out);
}

// round 11
// speedup vs baseline: 1.0012x; 1.0012x over previous
#include <cuda_runtime.h>
#include <cstdint>

// MixtureCrossattention, per batch b: C = [e1|e2] (16x576), e = patch_embed(x).
// For query col q (0..575): w_p = lam(p,q) * softmax-term of C[:,q]·C[:,p];
//   q >= 288 -> x3 output col q-288 (lam .7 on e1 keys / .3 on e2)
//   q <  288 -> x4 output col q     (lam .3 on e1 keys / .7 on e2)
// (reference's batch-0 block-transpose is a no-op: e2^T e2 block is symmetric)
//
// One CTA per batch, 192 threads, THREE queries per thread (t, t+192, t+384):
// each 64B key broadcast from smem feeds 48 warp-fma2 instead of 16, moving the
// kernel off the LDS/RF broadcast-return bound onto the fma pipe.
// lambda folded into exponent bias: w = 2^(s*log2e + log2 lam) = lam * e^s.

#define LOG2E   1.4426950408889634f
#define LOG2_07 (-0.5145731728297583f)
#define LOG2_03 (-1.7369655941662063f)

typedef unsigned long long ull;

__device__ __forceinline__ ull pack2(float lo, float hi) {
    ull r; asm("mov.b64 %0, {%1, %2};" : "=l"(r) : "f"(lo), "f"(hi)); return r;
}
__device__ __forceinline__ void unpack2(ull v, float &lo, float &hi) {
    asm("mov.b64 {%0, %1}, %2;" : "=f"(lo), "=f"(hi) : "l"(v));
}
__device__ __forceinline__ ull fma2(ull a, ull b, ull c) {
    ull d; asm("fma.rn.f32x2 %0, %1, %2, %3;" : "=l"(d) : "l"(a), "l"(b), "l"(c)); return d;
}
__device__ __forceinline__ float ex2a(float x) {
    float y; asm("ex2.approx.f32 %0, %1;" : "=f"(y) : "f"(x)); return y;
}

__global__ __launch_bounds__(192, 2)
void mixca_kernel(const float* __restrict__ x1,
                  const float* __restrict__ x2,
                  float* __restrict__ out)
{
    // phase 1: sB[j*16 + i] = C[i][j]   (576 keys x 16 dims, 36.9 KB)
    // phase 2: sB[q*17 + i] = output staging (576 x 17, 39.2 KB)
    __shared__ __align__(16) float sB[576 * 17];

    const int b = blockIdx.x;
    const int t = threadIdx.x;   // 0..191

    // ---- Load + patch-embed both inputs ----
    {
        const float* src0 = x1 + (size_t)b * 4608;
        const float* src1 = x2 + (size_t)b * 4608;
        #pragma unroll
        for (int e = 0; e < 2; e++) {
            const float* src = (e == 0) ? src0 : src1;
            #pragma unroll
            for (int k = 0; k < 24; k++) {
                int g = t + k * 192;           // linear idx into [32][12][12]
                float v = src[g];
                int c   = g / 144;
                int rem = g - c * 144;
                int r   = rem / 12;
                int s   = rem - r * 12;
                int h = r / 3, p1 = r - h * 3;
                int w = s / 3, p2 = s - w * 3;
                int i = h * 4 + w;                        // 0..15
                int j = (p1 * 3 + p2) * 32 + c + e * 288; // 0..575
                sB[j * 16 + i] = v;
            }
        }
    }
    __syncthreads();

    // ---- Three query vectors: cols t, t+192, t+384; dims packed, *log2(e) ----
    ull qv[3][8];
    float bseg0[3], bseg1[3];
    #pragma unroll
    for (int j = 0; j < 3; j++) {
        const int q = t + 192 * j;
        const float4* qp = reinterpret_cast<const float4*>(&sB[q * 16]);
        #pragma unroll
        for (int u = 0; u < 4; u++) {
            float4 qq = qp[u];
            qv[j][2 * u]     = pack2(qq.x * LOG2E, qq.y * LOG2E);
            qv[j][2 * u + 1] = pack2(qq.z * LOG2E, qq.w * LOG2E);
        }
        bseg0[j] = (q >= 288) ? LOG2_07 : LOG2_03;  // keys 0..287 (e1)
        bseg1[j] = (q >= 288) ? LOG2_03 : LOG2_07;  // keys 288..575 (e2)
    }

    ull acc[3][8];
    #pragma unroll
    for (int j = 0; j < 3; j++)
        #pragma unroll
        for (int u = 0; u < 8; u++) acc[j][u] = 0ull;
    float sw[3][2] = {{0.f,0.f},{0.f,0.f},{0.f,0.f}};

    #pragma unroll 1
    for (int seg = 0; seg < 2; seg++) {
        ull bias[3];
        #pragma unroll
        for (int j = 0; j < 3; j++)
            bias[j] = pack2(seg ? bseg1[j] : bseg0[j], 0.0f);
        float s0 = 0.f, s1 = 0.f, s2 = 0.f;
        const ulonglong2* base =
            reinterpret_cast<const ulonglong2*>(&sB[seg * 288 * 16]);

        #pragma unroll 1
        for (int c = 0; c < 288; c++) {
            // one key column: 16 dims, loaded once, feeds 3 queries
            ulonglong2 k0 = base[c * 4 + 0];
            ulonglong2 k1 = base[c * 4 + 1];
            ulonglong2 k2 = base[c * 4 + 2];
            ulonglong2 k3 = base[c * 4 + 3];

            ull sc0 = fma2(qv[0][0], k0.x, bias[0]);
            ull sc1 = fma2(qv[1][0], k0.x, bias[1]);
            ull sc2 = fma2(qv[2][0], k0.x, bias[2]);
            sc0 = fma2(qv[0][1], k0.y, sc0);
            sc1 = fma2(qv[1][1], k0.y, sc1);
            sc2 = fma2(qv[2][1], k0.y, sc2);
            sc0 = fma2(qv[0][2], k1.x, sc0);
            sc1 = fma2(qv[1][2], k1.x, sc1);
            sc2 = fma2(qv[2][2], k1.x, sc2);
            sc0 = fma2(qv[0][3], k1.y, sc0);
            sc1 = fma2(qv[1][3], k1.y, sc1);
            sc2 = fma2(qv[2][3], k1.y, sc2);
            sc0 = fma2(qv[0][4], k2.x, sc0);
            sc1 = fma2(qv[1][4], k2.x, sc1);
            sc2 = fma2(qv[2][4], k2.x, sc2);
            sc0 = fma2(qv[0][5], k2.y, sc0);
            sc1 = fma2(qv[1][5], k2.y, sc1);
            sc2 = fma2(qv[2][5], k2.y, sc2);
            sc0 = fma2(qv[0][6], k3.x, sc0);
            sc1 = fma2(qv[1][6], k3.x, sc1);
            sc2 = fma2(qv[2][6], k3.x, sc2);
            sc0 = fma2(qv[0][7], k3.y, sc0);
            sc1 = fma2(qv[1][7], k3.y, sc1);
            sc2 = fma2(qv[2][7], k3.y, sc2);

            float lo, hi;
            unpack2(sc0, lo, hi);  float w0 = ex2a(lo + hi);
            unpack2(sc1, lo, hi);  float w1 = ex2a(lo + hi);
            unpack2(sc2, lo, hi);  float w2 = ex2a(lo + hi);
            s0 += w0;  s1 += w1;  s2 += w2;
            ull w0p = pack2(w0, w0);
            ull w1p = pack2(w1, w1);
            ull w2p = pack2(w2, w2);

            acc[0][0] = fma2(w0p, k0.x, acc[0][0]);
            acc[1][0] = fma2(w1p, k0.x, acc[1][0]);
            acc[2][0] = fma2(w2p, k0.x, acc[2][0]);
            acc[0][1] = fma2(w0p, k0.y, acc[0][1]);
            acc[1][1] = fma2(w1p, k0.y, acc[1][1]);
            acc[2][1] = fma2(w2p, k0.y, acc[2][1]);
            acc[0][2] = fma2(w0p, k1.x, acc[0][2]);
            acc[1][2] = fma2(w1p, k1.x, acc[1][2]);
            acc[2][2] = fma2(w2p, k1.x, acc[2][2]);
            acc[0][3] = fma2(w0p, k1.y, acc[0][3]);
            acc[1][3] = fma2(w1p, k1.y, acc[1][3]);
            acc[2][3] = fma2(w2p, k1.y, acc[2][3]);
            acc[0][4] = fma2(w0p, k2.x, acc[0][4]);
            acc[1][4] = fma2(w1p, k2.x, acc[1][4]);
            acc[2][4] = fma2(w2p, k2.x, acc[2][4]);
            acc[0][5] = fma2(w0p, k2.y, acc[0][5]);
            acc[1][5] = fma2(w1p, k2.y, acc[1][5]);
            acc[2][5] = fma2(w2p, k2.y, acc[2][5]);
            acc[0][6] = fma2(w0p, k3.x, acc[0][6]);
            acc[1][6] = fma2(w1p, k3.x, acc[1][6]);
            acc[2][6] = fma2(w2p, k3.x, acc[2][6]);
            acc[0][7] = fma2(w0p, k3.y, acc[0][7]);
            acc[1][7] = fma2(w1p, k3.y, acc[1][7]);
            acc[2][7] = fma2(w2p, k3.y, acc[2][7]);
        }
        sw[0][seg] = s0;  sw[1][seg] = s1;  sw[2][seg] = s2;
    }

    // denominators: Z = sw_seg0/lam_seg0 + sw_seg1/lam_seg1
    float inv[3];
    #pragma unroll
    for (int j = 0; j < 3; j++) {
        const int q = t + 192 * j;
        const float iA = (q >= 288) ? (1.0f / 0.7f) : (1.0f / 0.3f);
        const float iB = (q >= 288) ? (1.0f / 0.3f) : (1.0f / 0.7f);
        inv[j] = 1.0f / (sw[j][0] * iA + sw[j][1] * iB);
    }

    __syncthreads();          // keys no longer needed; reuse sB as staging
    #pragma unroll
    for (int j = 0; j < 3; j++) {
        const int q = t + 192 * j;
        #pragma unroll
        for (int u = 0; u < 8; u++) {
            float lo, hi;
            unpack2(acc[j][u], lo, hi);
            sB[q * 17 + 2 * u]     = lo * inv[j];
            sB[q * 17 + 2 * u + 1] = hi * inv[j];
        }
    }
    __syncthreads();

    // ---- Coalesced un-patch stores: x3 block (queries 288+tt), then x4 (tt) ----
    #pragma unroll
    for (int half = 0; half < 2; half++) {
        float* dst = out + ((size_t)half * 512 + (size_t)b) * 4608;
        #pragma unroll
        for (int k = 0; k < 24; k++) {
            int g = t + k * 192;
            int c   = g / 144;
            int rem = g - c * 144;
            int r   = rem / 12;
            int s   = rem - r * 12;
            int h = r / 3, p1 = r - h * 3;
            int w = s / 3, p2 = s - w * 3;
            int i  = h * 4 + w;
            int tt = (p1 * 3 + p2) * 32 + c;
            int q  = (half == 0) ? (288 + tt) : tt;
            dst[g] = sB[q * 17 + i];
        }
    }
}

extern "C" void kernel_launch(void* const* d_in, const int* in_sizes, int n_in,
                              void* d_out, int out_size)
{
    const float* x1 = (const float*)d_in[0];
    const float* x2 = (const float*)d_in[1];
    float* out = (float*)d_out;
    mixca_kernel<<<512, 192>>>(x1, x2, out);
}

// round 12
// speedup vs baseline: 1.1905x; 1.1890x over previous
#include <cuda_runtime.h>
#include <cstdint>

// MixtureCrossattention via warp-level tf32 tensor-core MMA.
// Per batch: C = [e1|e2] (16 dims x 576 cols). W = lam .* exp(C^T C) is SYMMETRIC
// (lam(q,p)=0.7 iff q,p in different 288-halves), Out[:,q] = (C*W)[:,q] / Z_q,
// Z_q = sum_p exp(S[q,p]) reconstructed from lam-folded sums per segment.
// MMA1 (scores): 3xTF32 split precision (hi=top 19 bits, lo=residual) -> ~1e-6.
// MMA2 (C*W):    2xTF32 on C (hi+lo), W truncated to tf32 consistently in
//                numerator and denominator.
// Grid (512 batches, 3 query-blocks of 192). CTA = 384 thr = 12 warps,
// warp = 16 queries, loop 18 key tiles of 32.

#define LOG2E   1.4426950408889634f
#define LOG2_07 (-0.5145731728297583f)
#define LOG2_03 (-1.7369655941662063f)

#define WSC 20   // sCt row stride (conflict-free for frag patterns)
#define WSW 36   // wbuf row stride

__device__ __forceinline__ void mma_tf32(float c[4], const uint32_t a[4],
                                         uint32_t b0, uint32_t b1) {
    asm volatile(
        "mma.sync.aligned.m16n8k8.row.col.f32.tf32.tf32.f32 "
        "{%0,%1,%2,%3}, {%4,%5,%6,%7}, {%8,%9}, {%0,%1,%2,%3};"
        : "+f"(c[0]), "+f"(c[1]), "+f"(c[2]), "+f"(c[3])
        : "r"(a[0]), "r"(a[1]), "r"(a[2]), "r"(a[3]), "r"(b0), "r"(b1));
}
__device__ __forceinline__ float ex2a(float x) {
    float y; asm("ex2.approx.f32 %0, %1;" : "=f"(y) : "f"(x)); return y;
}
__device__ __forceinline__ uint32_t fu(float x) { return __float_as_uint(x); }

__global__ __launch_bounds__(384, 1)
void mixca_mma(const float* __restrict__ x1,
               const float* __restrict__ x2,
               float* __restrict__ out)
{
    extern __shared__ float smem[];
    float* sH = smem;                  // [576][WSC]  C hi (tf32-exact)
    float* sL = smem + 576 * WSC;      // [576][WSC]  C lo ; reused as sO
    float* wb = smem + 2 * 576 * WSC;  // [12][16][WSW] per-warp W staging

    const int b   = blockIdx.x;
    const int z   = blockIdx.y;        // query block 0..2
    const int t   = threadIdx.x;
    const int wid = t >> 5, lid = t & 31;
    const int grp = lid >> 2, tig = lid & 3;
    const int zbase = z * 192;

    // ---- embed both inputs: sCt[j][i] = C[i][j], split hi/lo ----
    {
        const float* src0 = x1 + (size_t)b * 4608;
        const float* src1 = x2 + (size_t)b * 4608;
        #pragma unroll
        for (int e = 0; e < 2; e++) {
            const float* src = (e == 0) ? src0 : src1;
            #pragma unroll
            for (int k = 0; k < 12; k++) {
                int g = t + k * 384;
                float v = src[g];
                int c   = g / 144;
                int rem = g - c * 144;
                int r   = rem / 12;
                int s   = rem - r * 12;
                int h = r / 3, p1 = r - h * 3;
                int w = s / 3, p2 = s - w * 3;
                int i = h * 4 + w;
                int j = (p1 * 3 + p2) * 32 + c + e * 288;
                float hv = __uint_as_float(__float_as_uint(v) & 0xFFFFE000u);
                sH[j * WSC + i] = hv;
                sL[j * WSC + i] = v - hv;
            }
        }
    }
    __syncthreads();

    const int qbase = zbase + wid * 16;        // this warp's 16 queries
    const bool x3q  = (qbase >= 288);
    const float bias0 = x3q ? LOG2_07 : LOG2_03;   // keys 0..287 (e1)
    const float bias1 = x3q ? LOG2_03 : LOG2_07;   // keys 288..575 (e2)

    // A1 fragments (queries x dims), hi & lo, loaded once
    uint32_t aH[2][4], aL[2][4];
    #pragma unroll
    for (int ks = 0; ks < 2; ks++) {
        int r0 = (qbase + grp) * WSC + ks * 8 + tig;
        int r1 = r0 + 8 * WSC;
        aH[ks][0] = fu(sH[r0]);     aH[ks][1] = fu(sH[r1]);
        aH[ks][2] = fu(sH[r0 + 4]); aH[ks][3] = fu(sH[r1 + 4]);
        aL[ks][0] = fu(sL[r0]);     aL[ks][1] = fu(sL[r1]);
        aL[ks][2] = fu(sL[r0 + 4]); aL[ks][3] = fu(sL[r1 + 4]);
    }

    float o0[4] = {0.f, 0.f, 0.f, 0.f};   // D2 dims 0..7
    float o1[4] = {0.f, 0.f, 0.f, 0.f};   // D2 dims 8..15
    float zac[4] = {0.f, 0.f, 0.f, 0.f};  // [seg*2 + rowhalf]
    float* wrow = wb + wid * 16 * WSW;

    #pragma unroll 1
    for (int kt = 0; kt < 18; kt++) {
        const int pbase = kt * 32;
        const float bias = (kt < 9) ? bias0 : bias1;
        const int zi = (kt < 9) ? 0 : 2;

        // ---- MMA1: S-tile 16x32 (4 n-blocks), 3xTF32; then exp -> wbuf ----
        #pragma unroll
        for (int nb = 0; nb < 4; nb++) {
            const int np = pbase + nb * 8;
            int rb = (np + grp) * WSC + tig;
            uint32_t bh00 = fu(sH[rb]),      bh01 = fu(sH[rb + 4]);
            uint32_t bh10 = fu(sH[rb + 8]),  bh11 = fu(sH[rb + 12]);
            uint32_t bl00 = fu(sL[rb]),      bl01 = fu(sL[rb + 4]);
            uint32_t bl10 = fu(sL[rb + 8]),  bl11 = fu(sL[rb + 12]);

            float c[4] = {0.f, 0.f, 0.f, 0.f};
            mma_tf32(c, aH[0], bh00, bh01);
            mma_tf32(c, aH[1], bh10, bh11);
            mma_tf32(c, aH[0], bl00, bl01);
            mma_tf32(c, aH[1], bl10, bl11);
            mma_tf32(c, aL[0], bh00, bh01);
            mma_tf32(c, aL[1], bh10, bh11);

            float w0 = ex2a(fmaf(c[0], LOG2E, bias));
            float w1 = ex2a(fmaf(c[1], LOG2E, bias));
            float w2 = ex2a(fmaf(c[2], LOG2E, bias));
            float w3 = ex2a(fmaf(c[3], LOG2E, bias));
            // truncate to tf32 so numerator GEMM and denominator agree exactly
            w0 = __uint_as_float(fu(w0) & 0xFFFFE000u);
            w1 = __uint_as_float(fu(w1) & 0xFFFFE000u);
            w2 = __uint_as_float(fu(w2) & 0xFFFFE000u);
            w3 = __uint_as_float(fu(w3) & 0xFFFFE000u);
            zac[zi]     += w0 + w1;
            zac[zi + 1] += w2 + w3;

            *(float2*)&wrow[grp * WSW + nb * 8 + 2 * tig]       = make_float2(w0, w1);
            *(float2*)&wrow[(grp + 8) * WSW + nb * 8 + 2 * tig] = make_float2(w2, w3);
        }
        __syncwarp();

        // ---- MMA2: O(16x16) += W(16x32) x C_keys^T(32x16), 2xTF32 on C ----
        #pragma unroll
        for (int ks2 = 0; ks2 < 4; ks2++) {
            uint32_t a2[4];
            int wi = grp * WSW + ks2 * 8 + tig;
            a2[0] = fu(wrow[wi]);           a2[1] = fu(wrow[wi + 8 * WSW]);
            a2[2] = fu(wrow[wi + 4]);       a2[3] = fu(wrow[wi + 8 * WSW + 4]);

            int kr = (pbase + ks2 * 8 + tig) * WSC;
            uint32_t b0h = fu(sH[kr + grp]),           b1h = fu(sH[kr + 4 * WSC + grp]);
            uint32_t b0l = fu(sL[kr + grp]),           b1l = fu(sL[kr + 4 * WSC + grp]);
            mma_tf32(o0, a2, b0h, b1h);
            mma_tf32(o0, a2, b0l, b1l);
            uint32_t c0h = fu(sH[kr + 8 + grp]),       c1h = fu(sH[kr + 4 * WSC + 8 + grp]);
            uint32_t c0l = fu(sL[kr + 8 + grp]),       c1l = fu(sL[kr + 4 * WSC + 8 + grp]);
            mma_tf32(o1, a2, c0h, c1h);
            mma_tf32(o1, a2, c0l, c1l);
        }
        __syncwarp();   // wbuf reads done before next tile overwrites
    }

    // ---- Z: quad-reduce (lanes of same grp hold same rows) ----
    #pragma unroll
    for (int i2 = 0; i2 < 4; i2++) {
        zac[i2] += __shfl_xor_sync(0xffffffffu, zac[i2], 1);
        zac[i2] += __shfl_xor_sync(0xffffffffu, zac[i2], 2);
    }
    const float il0 = x3q ? (1.f / 0.7f) : (1.f / 0.3f);
    const float il1 = x3q ? (1.f / 0.3f) : (1.f / 0.7f);
    const float ivg  = 1.f / (zac[0] * il0 + zac[2] * il1);   // rows grp
    const float ivg8 = 1.f / (zac[1] * il0 + zac[3] * il1);   // rows grp+8

    __syncthreads();            // all warps done reading sL (B2 lo)
    float* sO = sL;             // reuse as [576][WSC] output staging
    {
        int ro = (qbase + grp) * WSC + 2 * tig;
        sO[ro]     = o0[0] * ivg;   sO[ro + 1] = o0[1] * ivg;
        sO[ro + 8] = o1[0] * ivg;   sO[ro + 9] = o1[1] * ivg;
        int r8 = ro + 8 * WSC;
        sO[r8]     = o0[2] * ivg8;  sO[r8 + 1] = o0[3] * ivg8;
        sO[r8 + 8] = o1[2] * ivg8;  sO[r8 + 9] = o1[3] * ivg8;
    }
    __syncthreads();

    // ---- guarded coalesced un-patch stores (this CTA owns 192 query cols) ----
    #pragma unroll
    for (int half = 0; half < 2; half++) {
        float* dst = out + ((size_t)half * 512 + (size_t)b) * 4608;
        #pragma unroll
        for (int k = 0; k < 12; k++) {
            int g = t + k * 384;
            int c   = g / 144;
            int rem = g - c * 144;
            int r   = rem / 12;
            int s   = rem - r * 12;
            int h = r / 3, p1 = r - h * 3;
            int w = s / 3, p2 = s - w * 3;
            int i  = h * 4 + w;
            int tt = (p1 * 3 + p2) * 32 + c;
            int q  = (half == 0) ? (288 + tt) : tt;   // x3 <- queries 288+tt
            if (q >= zbase && q < zbase + 192)
                dst[g] = sO[q * WSC + i];
        }
    }
}

extern "C" void kernel_launch(void* const* d_in, const int* in_sizes, int n_in,
                              void* d_out, int out_size)
{
    const float* x1 = (const float*)d_in[0];
    const float* x2 = (const float*)d_in[1];
    float* out = (float*)d_out;
    const int smem_bytes = (2 * 576 * WSC + 12 * 16 * WSW) * sizeof(float); // 119808
    cudaFuncSetAttribute(mixca_mma, cudaFuncAttributeMaxDynamicSharedMemorySize,
                         smem_bytes);
    dim3 grid(512, 3);
    mixca_mma<<<grid, 384, smem_bytes>>>(x1, x2, out);
}

// round 14
// speedup vs baseline: 1.5248x; 1.2808x over previous
#include <cuda_runtime.h>
#include <cstdint>

// MixtureCrossattention via warp-level tf32 MMA, v2 (LDS-minimized).
// Per batch: C = [e1|e2] (16 x 576); W = lam .* exp(C^T C); Out[:,q] = (C*W)[:,q]/Z_q.
// CTA = (batch, half): 288 thr = 9 warps x 32 queries. grid (512,2):
//   z=0 -> queries 0..287   -> x4 output block
//   z=1 -> queries 288..575 -> x3 output block
// MMA1 (scores): 3xTF32 split (hi/lo). MMA2 (C*W): hi-only C (tf32), W truncated
// to tf32 consistently in numerator and denominator.
// LDS layout: sH/sL key-major stride 20 (8-row frags conflict-free);
// sD dim-major stride 580 (=4 mod 32: MMA2 B frags conflict-free).

#define LOG2E   1.4426950408889634f
#define LOG2_07 (-0.5145731728297583f)
#define LOG2_03 (-1.7369655941662063f)

#define WSC 20
#define SDS 580
#define WSW 36

__device__ __forceinline__ void mma_tf32(float c[4], const uint32_t a[4],
                                         uint32_t b0, uint32_t b1) {
    asm volatile(
        "mma.sync.aligned.m16n8k8.row.col.f32.tf32.tf32.f32 "
        "{%0,%1,%2,%3}, {%4,%5,%6,%7}, {%8,%9}, {%0,%1,%2,%3};"
        : "+f"(c[0]), "+f"(c[1]), "+f"(c[2]), "+f"(c[3])
        : "r"(a[0]), "r"(a[1]), "r"(a[2]), "r"(a[3]), "r"(b0), "r"(b1));
}
__device__ __forceinline__ float ex2a(float x) {
    float y; asm("ex2.approx.f32 %0, %1;" : "=f"(y) : "f"(x)); return y;
}
__device__ __forceinline__ uint32_t fu(float x) { return __float_as_uint(x); }
__device__ __forceinline__ float trunc_tf32(float x) {
    return __uint_as_float(__float_as_uint(x) & 0xFFFFE000u);
}

__global__ __launch_bounds__(288, 1)
void mixca_mma2(const float* __restrict__ x1,
                const float* __restrict__ x2,
                float* __restrict__ out)
{
    extern __shared__ float smem[];
    float* sH = smem;              // [576][WSC]  C^T hi (key-major)
    float* sL = smem + 11520;      // [576][WSC]  C^T lo ; reused as sO
    float* sD = smem + 23040;      // [16][SDS]   C hi (dim-major, MMA2 B)
    float* wb = smem + 32320;      // [9][32][WSW] per-warp W staging

    const int b = blockIdx.x;
    const int z = blockIdx.y;          // 0 -> x4 half, 1 -> x3 half
    const int t = threadIdx.x;
    const int wid = t >> 5, lid = t & 31;
    const int grp = lid >> 2, tig = lid & 3;
    const int zbase = z * 288;

    // ---- embed both inputs; fill sH, sL (key-major) + sD (dim-major hi) ----
    {
        const float* src0 = x1 + (size_t)b * 4608;
        const float* src1 = x2 + (size_t)b * 4608;
        #pragma unroll
        for (int e = 0; e < 2; e++) {
            const float* src = (e == 0) ? src0 : src1;
            #pragma unroll
            for (int k = 0; k < 16; k++) {
                int g = t + k * 288;
                float v = src[g];
                int c   = g / 144;
                int rem = g - c * 144;
                int r   = rem / 12;
                int s   = rem - r * 12;
                int h = r / 3, p1 = r - h * 3;
                int w = s / 3, p2 = s - w * 3;
                int i = h * 4 + w;
                int j = (p1 * 3 + p2) * 32 + c + e * 288;
                float hv = trunc_tf32(v);
                sH[j * WSC + i] = hv;
                sL[j * WSC + i] = v - hv;
                sD[i * SDS + j] = hv;
            }
        }
    }
    __syncthreads();

    const bool x3q  = (z == 1);
    const float bias0 = x3q ? LOG2_07 : LOG2_03;   // keys 0..287 (e1)
    const float bias1 = x3q ? LOG2_03 : LOG2_07;   // keys 288..575 (e2)

    // A1 fragments for 2 m-tiles (32 queries), hi & lo, loaded once
    uint32_t aH[2][2][4], aL[2][2][4];
    #pragma unroll
    for (int mh = 0; mh < 2; mh++) {
        #pragma unroll
        for (int ks = 0; ks < 2; ks++) {
            int r0 = (zbase + wid * 32 + mh * 16 + grp) * WSC + ks * 8 + tig;
            int r1 = r0 + 8 * WSC;
            aH[mh][ks][0] = fu(sH[r0]);     aH[mh][ks][1] = fu(sH[r1]);
            aH[mh][ks][2] = fu(sH[r0 + 4]); aH[mh][ks][3] = fu(sH[r1 + 4]);
            aL[mh][ks][0] = fu(sL[r0]);     aL[mh][ks][1] = fu(sL[r1]);
            aL[mh][ks][2] = fu(sL[r0 + 4]); aL[mh][ks][3] = fu(sL[r1 + 4]);
        }
    }

    float o[2][2][4];                 // [mh][dim-half][frag]
    #pragma unroll
    for (int mh = 0; mh < 2; mh++)
        #pragma unroll
        for (int d = 0; d < 2; d++)
            #pragma unroll
            for (int u = 0; u < 4; u++) o[mh][d][u] = 0.f;
    float zac[2][4] = {{0.f,0.f,0.f,0.f},{0.f,0.f,0.f,0.f}};  // [mh][seg*2+rowhalf]
    float* wrow = wb + wid * 32 * WSW;

    #pragma unroll 1
    for (int kt = 0; kt < 18; kt++) {
        const int pbase = kt * 32;
        const float bias = (kt < 9) ? bias0 : bias1;
        const int zi = (kt < 9) ? 0 : 2;

        // ---- MMA1: S-tiles (2x16)x32, 3xTF32; exp -> wbuf ----
        #pragma unroll
        for (int nb = 0; nb < 4; nb++) {
            int rb = (pbase + nb * 8 + grp) * WSC + tig;
            // B frag: n = key row (rb row), k = dim (within-row offset).
            // k-group 0: dims 0..7 -> +0, +4 ; k-group 1: dims 8..15 -> +8, +12
            uint32_t bh00 = fu(sH[rb]),      bh01 = fu(sH[rb + 4]);
            uint32_t bh10 = fu(sH[rb + 8]),  bh11 = fu(sH[rb + 12]);
            uint32_t bl00 = fu(sL[rb]),      bl01 = fu(sL[rb + 4]);
            uint32_t bl10 = fu(sL[rb + 8]),  bl11 = fu(sL[rb + 12]);

            #pragma unroll
            for (int mh = 0; mh < 2; mh++) {
                float c[4] = {0.f, 0.f, 0.f, 0.f};
                mma_tf32(c, aH[mh][0], bh00, bh01);
                mma_tf32(c, aH[mh][1], bh10, bh11);
                mma_tf32(c, aH[mh][0], bl00, bl01);
                mma_tf32(c, aH[mh][1], bl10, bl11);
                mma_tf32(c, aL[mh][0], bh00, bh01);
                mma_tf32(c, aL[mh][1], bh10, bh11);

                float w0 = trunc_tf32(ex2a(fmaf(c[0], LOG2E, bias)));
                float w1 = trunc_tf32(ex2a(fmaf(c[1], LOG2E, bias)));
                float w2 = trunc_tf32(ex2a(fmaf(c[2], LOG2E, bias)));
                float w3 = trunc_tf32(ex2a(fmaf(c[3], LOG2E, bias)));
                zac[mh][zi]     += w0 + w1;
                zac[mh][zi + 1] += w2 + w3;
                *(float2*)&wrow[(mh * 16 + grp) * WSW + nb * 8 + 2 * tig]     = make_float2(w0, w1);
                *(float2*)&wrow[(mh * 16 + grp + 8) * WSW + nb * 8 + 2 * tig] = make_float2(w2, w3);
            }
        }
        __syncwarp();

        // ---- MMA2: O(2x16 x 16) += W x C_keys^T, hi-only C, conflict-free B ----
        #pragma unroll
        for (int ks2 = 0; ks2 < 4; ks2++) {
            int kb = pbase + ks2 * 8;
            uint32_t b0h = fu(sD[grp * SDS + kb + tig]);
            uint32_t b1h = fu(sD[grp * SDS + kb + tig + 4]);
            uint32_t c0h = fu(sD[(grp + 8) * SDS + kb + tig]);
            uint32_t c1h = fu(sD[(grp + 8) * SDS + kb + tig + 4]);

            #pragma unroll
            for (int mh = 0; mh < 2; mh++) {
                uint32_t a2[4];
                int wi = (mh * 16 + grp) * WSW + ks2 * 8 + tig;
                a2[0] = fu(wrow[wi]);      a2[1] = fu(wrow[wi + 8 * WSW]);
                a2[2] = fu(wrow[wi + 4]);  a2[3] = fu(wrow[wi + 8 * WSW + 4]);
                mma_tf32(o[mh][0], a2, b0h, b1h);
                mma_tf32(o[mh][1], a2, c0h, c1h);
            }
        }
        __syncwarp();
    }

    // ---- Z: quad-reduce ----
    #pragma unroll
    for (int mh = 0; mh < 2; mh++)
        #pragma unroll
        for (int i2 = 0; i2 < 4; i2++) {
            zac[mh][i2] += __shfl_xor_sync(0xffffffffu, zac[mh][i2], 1);
            zac[mh][i2] += __shfl_xor_sync(0xffffffffu, zac[mh][i2], 2);
        }
    const float il0 = x3q ? (1.f / 0.7f) : (1.f / 0.3f);
    const float il1 = x3q ? (1.f / 0.3f) : (1.f / 0.7f);

    __syncthreads();            // all warps done with sL
    float* sO = sL;             // [288 local queries][WSC]
    #pragma unroll
    for (int mh = 0; mh < 2; mh++) {
        const float ivg  = 1.f / (zac[mh][0] * il0 + zac[mh][2] * il1);
        const float ivg8 = 1.f / (zac[mh][1] * il0 + zac[mh][3] * il1);
        int ro = (wid * 32 + mh * 16 + grp) * WSC + 2 * tig;
        sO[ro]     = o[mh][0][0] * ivg;   sO[ro + 1] = o[mh][0][1] * ivg;
        sO[ro + 8] = o[mh][1][0] * ivg;   sO[ro + 9] = o[mh][1][1] * ivg;
        int r8 = ro + 8 * WSC;
        sO[r8]     = o[mh][0][2] * ivg8;  sO[r8 + 1] = o[mh][0][3] * ivg8;
        sO[r8 + 8] = o[mh][1][2] * ivg8;  sO[r8 + 9] = o[mh][1][3] * ivg8;
    }
    __syncthreads();

    // ---- coalesced un-patch store; CTA owns exactly one output half ----
    float* dst = out + ((size_t)((z == 1) ? 0 : 1) * 512 + (size_t)b) * 4608;
    #pragma unroll
    for (int k = 0; k < 16; k++) {
        int g = t + k * 288;
        int c   = g / 144;
        int rem = g - c * 144;
        int r   = rem / 12;
        int s   = rem - r * 12;
        int h = r / 3, p1 = r - h * 3;
        int w = s / 3, p2 = s - w * 3;
        int i  = h * 4 + w;
        int tt = (p1 * 3 + p2) * 32 + c;   // local query col 0..287
        dst[g] = sO[tt * WSC + i];
    }
}

extern "C" void kernel_launch(void* const* d_in, const int* in_sizes, int n_in,
                              void* d_out, int out_size)
{
    const float* x1 = (const float*)d_in[0];
    const float* x2 = (const float*)d_in[1];
    float* out = (float*)d_out;
    const int smem_bytes = (11520 + 11520 + 16 * SDS + 9 * 32 * WSW) * sizeof(float);
    cudaFuncSetAttribute(mixca_mma2, cudaFuncAttributeMaxDynamicSharedMemorySize,
                         smem_bytes);
    dim3 grid(512, 2);
    mixca_mma2<<<grid, 288, smem_bytes>>>(x1, x2, out);
}

// round 15
// speedup vs baseline: 1.9949x; 1.3083x over previous
#include <cuda_runtime.h>
#include <cstdint>

// MixtureCrossattention via warp-level tf32 MMA, v3 (zero-copy W relay).
// Per batch: C = [e1|e2] (16 x 576); W = lam .* exp(C^T C); Out[:,q] = (C*W)[:,q]/Z_q.
// CTA = (batch, half): 288 thr = 9 warps x 32 queries; grid (512,2); 2 CTAs/SM.
//
// Fragment trick: MMA2 sums over keys with permuted k-order sigma=(0,2,4,6,1,3,5,7).
// Under sigma, MMA1's C-output fragment {c0,c2,c1,c3} IS MMA2's A fragment (no
// smem/shuffle relay), and MMA2's B fragment reads the key-major sH directly at
// rows (2tig, 2tig+1) - conflict-free (banks 8*tig+grp).
// MMA1 (scores): 3xTF32 split (hi/lo). MMA2: hi-only C, W truncated to tf32
// consistently in numerator (HW tf32 convert) and denominator (explicit trunc).

#define LOG2E   1.4426950408889634f
#define LOG2_07 (-0.5145731728297583f)
#define LOG2_03 (-1.7369655941662063f)

#define WSC 20

__device__ __forceinline__ void mma_tf32(float c[4], const uint32_t a[4],
                                         uint32_t b0, uint32_t b1) {
    asm volatile(
        "mma.sync.aligned.m16n8k8.row.col.f32.tf32.tf32.f32 "
        "{%0,%1,%2,%3}, {%4,%5,%6,%7}, {%8,%9}, {%0,%1,%2,%3};"
        : "+f"(c[0]), "+f"(c[1]), "+f"(c[2]), "+f"(c[3])
        : "r"(a[0]), "r"(a[1]), "r"(a[2]), "r"(a[3]), "r"(b0), "r"(b1));
}
__device__ __forceinline__ float ex2a(float x) {
    float y; asm("ex2.approx.f32 %0, %1;" : "=f"(y) : "f"(x)); return y;
}
__device__ __forceinline__ uint32_t fu(float x) { return __float_as_uint(x); }
__device__ __forceinline__ float trunc_tf32(float x) {
    return __uint_as_float(__float_as_uint(x) & 0xFFFFE000u);
}

__global__ __launch_bounds__(288, 2)
void mixca_mma3(const float* __restrict__ x1,
                const float* __restrict__ x2,
                float* __restrict__ out)
{
    extern __shared__ float smem[];
    float* sH = smem;              // [576][WSC]  C^T hi (key-major, tf32-exact)
    float* sL = smem + 11520;      // [576][WSC]  C^T lo ; reused as sO

    const int b = blockIdx.x;
    const int z = blockIdx.y;          // 0 -> x4 half, 1 -> x3 half
    const int t = threadIdx.x;
    const int wid = t >> 5, lid = t & 31;
    const int grp = lid >> 2, tig = lid & 3;
    const int zbase = z * 288;

    // ---- embed both inputs; fill sH (hi) + sL (lo), key-major ----
    {
        const float* src0 = x1 + (size_t)b * 4608;
        const float* src1 = x2 + (size_t)b * 4608;
        #pragma unroll
        for (int e = 0; e < 2; e++) {
            const float* src = (e == 0) ? src0 : src1;
            #pragma unroll
            for (int k = 0; k < 16; k++) {
                int g = t + k * 288;
                float v = src[g];
                int c   = g / 144;
                int rem = g - c * 144;
                int r   = rem / 12;
                int s   = rem - r * 12;
                int h = r / 3, p1 = r - h * 3;
                int w = s / 3, p2 = s - w * 3;
                int i = h * 4 + w;
                int j = (p1 * 3 + p2) * 32 + c + e * 288;
                float hv = trunc_tf32(v);
                sH[j * WSC + i] = hv;
                sL[j * WSC + i] = v - hv;
            }
        }
    }
    __syncthreads();

    const bool x3q  = (z == 1);
    const float bias0 = x3q ? LOG2_07 : LOG2_03;   // keys 0..287 (e1)
    const float bias1 = x3q ? LOG2_03 : LOG2_07;   // keys 288..575 (e2)

    // A1 fragments for 2 m-tiles (32 queries), hi & lo, loaded once
    uint32_t aH[2][2][4], aL[2][2][4];
    #pragma unroll
    for (int mh = 0; mh < 2; mh++) {
        #pragma unroll
        for (int ks = 0; ks < 2; ks++) {
            int r0 = (zbase + wid * 32 + mh * 16 + grp) * WSC + ks * 8 + tig;
            int r1 = r0 + 8 * WSC;
            aH[mh][ks][0] = fu(sH[r0]);     aH[mh][ks][1] = fu(sH[r1]);
            aH[mh][ks][2] = fu(sH[r0 + 4]); aH[mh][ks][3] = fu(sH[r1 + 4]);
            aL[mh][ks][0] = fu(sL[r0]);     aL[mh][ks][1] = fu(sL[r1]);
            aL[mh][ks][2] = fu(sL[r0 + 4]); aL[mh][ks][3] = fu(sL[r1 + 4]);
        }
    }

    float o[2][2][4];                 // [mh][dim-half][frag]
    #pragma unroll
    for (int mh = 0; mh < 2; mh++)
        #pragma unroll
        for (int d = 0; d < 2; d++)
            #pragma unroll
            for (int u = 0; u < 4; u++) o[mh][d][u] = 0.f;
    float zac[2][4] = {{0.f,0.f,0.f,0.f},{0.f,0.f,0.f,0.f}};  // [mh][seg*2+rowhalf]

    #pragma unroll 1
    for (int kt = 0; kt < 18; kt++) {
        const int pbase = kt * 32;
        const float bias = (kt < 9) ? bias0 : bias1;
        const int zi = (kt < 9) ? 0 : 2;

        #pragma unroll
        for (int nb = 0; nb < 4; nb++) {
            const int kb = pbase + nb * 8;
            // MMA1 B frag: n = key (row kb+grp), k = dim (tig / tig+4 / +8 / +12)
            int rb = (kb + grp) * WSC + tig;
            uint32_t bh00 = fu(sH[rb]),      bh01 = fu(sH[rb + 4]);
            uint32_t bh10 = fu(sH[rb + 8]),  bh11 = fu(sH[rb + 12]);
            uint32_t bl00 = fu(sL[rb]),      bl01 = fu(sL[rb + 4]);
            uint32_t bl10 = fu(sL[rb + 8]),  bl11 = fu(sL[rb + 12]);

            // MMA2 B frag (sigma key order): kpos tig -> key 2tig, kpos tig+4 -> 2tig+1
            int rk0 = (kb + 2 * tig) * WSC;
            int rk1 = rk0 + WSC;
            uint32_t kb0 = fu(sH[rk0 + grp]),     kb1 = fu(sH[rk1 + grp]);      // dims 0..7
            uint32_t kc0 = fu(sH[rk0 + grp + 8]), kc1 = fu(sH[rk1 + grp + 8]);  // dims 8..15

            #pragma unroll
            for (int mh = 0; mh < 2; mh++) {
                float c[4] = {0.f, 0.f, 0.f, 0.f};
                mma_tf32(c, aH[mh][0], bh00, bh01);
                mma_tf32(c, aH[mh][1], bh10, bh11);
                mma_tf32(c, aH[mh][0], bl00, bl01);
                mma_tf32(c, aH[mh][1], bl10, bl11);
                mma_tf32(c, aL[mh][0], bh00, bh01);
                mma_tf32(c, aL[mh][1], bh10, bh11);

                // w-fragment: rows {grp, grp+8}, keys {2tig, 2tig+1}
                float w0 = trunc_tf32(ex2a(fmaf(c[0], LOG2E, bias)));
                float w1 = trunc_tf32(ex2a(fmaf(c[1], LOG2E, bias)));
                float w2 = trunc_tf32(ex2a(fmaf(c[2], LOG2E, bias)));
                float w3 = trunc_tf32(ex2a(fmaf(c[3], LOG2E, bias)));
                zac[mh][zi]     += w0 + w1;
                zac[mh][zi + 1] += w2 + w3;

                // MMA2 A frag under sigma = {w0, w2, w1, w3} -- no relay needed
                uint32_t a2[4] = { fu(w0), fu(w2), fu(w1), fu(w3) };
                mma_tf32(o[mh][0], a2, kb0, kb1);
                mma_tf32(o[mh][1], a2, kc0, kc1);
            }
        }
    }

    // ---- Z: quad-reduce (lanes of same grp hold same rows) ----
    #pragma unroll
    for (int mh = 0; mh < 2; mh++)
        #pragma unroll
        for (int i2 = 0; i2 < 4; i2++) {
            zac[mh][i2] += __shfl_xor_sync(0xffffffffu, zac[mh][i2], 1);
            zac[mh][i2] += __shfl_xor_sync(0xffffffffu, zac[mh][i2], 2);
        }
    const float il0 = x3q ? (1.f / 0.7f) : (1.f / 0.3f);
    const float il1 = x3q ? (1.f / 0.3f) : (1.f / 0.7f);

    __syncthreads();            // all warps done with sL
    float* sO = sL;             // [288 local queries][WSC]
    #pragma unroll
    for (int mh = 0; mh < 2; mh++) {
        const float ivg  = 1.f / (zac[mh][0] * il0 + zac[mh][2] * il1);
        const float ivg8 = 1.f / (zac[mh][1] * il0 + zac[mh][3] * il1);
        int ro = (wid * 32 + mh * 16 + grp) * WSC + 2 * tig;
        sO[ro]     = o[mh][0][0] * ivg;   sO[ro + 1] = o[mh][0][1] * ivg;
        sO[ro + 8] = o[mh][1][0] * ivg;   sO[ro + 9] = o[mh][1][1] * ivg;
        int r8 = ro + 8 * WSC;
        sO[r8]     = o[mh][0][2] * ivg8;  sO[r8 + 1] = o[mh][0][3] * ivg8;
        sO[r8 + 8] = o[mh][1][2] * ivg8;  sO[r8 + 9] = o[mh][1][3] * ivg8;
    }
    __syncthreads();

    // ---- coalesced un-patch store; CTA owns exactly one output half ----
    float* dst = out + ((size_t)((z == 1) ? 0 : 1) * 512 + (size_t)b) * 4608;
    #pragma unroll
    for (int k = 0; k < 16; k++) {
        int g = t + k * 288;
        int c   = g / 144;
        int rem = g - c * 144;
        int r   = rem / 12;
        int s   = rem - r * 12;
        int h = r / 3, p1 = r - h * 3;
        int w = s / 3, p2 = s - w * 3;
        int i  = h * 4 + w;
        int tt = (p1 * 3 + p2) * 32 + c;   // local query col 0..287
        dst[g] = sO[tt * WSC + i];
    }
}

extern "C" void kernel_launch(void* const* d_in, const int* in_sizes, int n_in,
                              void* d_out, int out_size)
{
    const float* x1 = (const float*)d_in[0];
    const float* x2 = (const float*)d_in[1];
    float* out = (float*)d_out;
    const int smem_bytes = 2 * 11520 * sizeof(float);   // 92160
    cudaFuncSetAttribute(mixca_mma3, cudaFuncAttributeMaxDynamicSharedMemorySize,
                         smem_bytes);
    dim3 grid(512, 2);
    mixca_mma3<<<grid, 288, smem_bytes>>>(x1, x2, out);
}

// round 16
// speedup vs baseline: 2.0198x; 1.0125x over previous
#include <cuda_runtime.h>
#include <cstdint>

// MixtureCrossattention via warp-level tf32 MMA, v4 (split MMA1 chains).
// Per batch: C = [e1|e2] (16 x 576); W = lam .* exp(C^T C); Out[:,q] = (C*W)[:,q]/Z_q.
// CTA = (batch, half): 288 thr = 9 warps x 32 queries; grid (512,2); 2 CTAs/SM.
//
// v3 trick kept: MMA2 sums keys in permuted order sigma=(0,2,4,6,1,3,5,7), so
// MMA1's C-output fragment {w0,w2,w1,w3} IS MMA2's A fragment (zero-copy relay)
// and MMA2's B reads key-major sH conflict-free at rows (2tig, 2tig+1).
// v4: MMA1's 6 dependent HMMAs split into two independent 3-chains (ca, cb),
// merged with 4 FADDs -> serial latency halved, 4 HMMA streams/warp with mh.
// MMA1: 3xTF32 split (hi/lo). MMA2: hi-only C; W truncated to tf32 consistently.

#define LOG2E   1.4426950408889634f
#define LOG2_07 (-0.5145731728297583f)
#define LOG2_03 (-1.7369655941662063f)

#define WSC 20

__device__ __forceinline__ void mma_tf32(float c[4], const uint32_t a[4],
                                         uint32_t b0, uint32_t b1) {
    asm volatile(
        "mma.sync.aligned.m16n8k8.row.col.f32.tf32.tf32.f32 "
        "{%0,%1,%2,%3}, {%4,%5,%6,%7}, {%8,%9}, {%0,%1,%2,%3};"
        : "+f"(c[0]), "+f"(c[1]), "+f"(c[2]), "+f"(c[3])
        : "r"(a[0]), "r"(a[1]), "r"(a[2]), "r"(a[3]), "r"(b0), "r"(b1));
}
__device__ __forceinline__ float ex2a(float x) {
    float y; asm("ex2.approx.f32 %0, %1;" : "=f"(y) : "f"(x)); return y;
}
__device__ __forceinline__ uint32_t fu(float x) { return __float_as_uint(x); }
__device__ __forceinline__ float trunc_tf32(float x) {
    return __uint_as_float(__float_as_uint(x) & 0xFFFFE000u);
}

__global__ __launch_bounds__(288, 2)
void mixca_mma4(const float* __restrict__ x1,
                const float* __restrict__ x2,
                float* __restrict__ out)
{
    extern __shared__ float smem[];
    float* sH = smem;              // [576][WSC]  C^T hi (key-major, tf32-exact)
    float* sL = smem + 11520;      // [576][WSC]  C^T lo ; reused as sO

    const int b = blockIdx.x;
    const int z = blockIdx.y;          // 0 -> x4 half, 1 -> x3 half
    const int t = threadIdx.x;
    const int wid = t >> 5, lid = t & 31;
    const int grp = lid >> 2, tig = lid & 3;
    const int zbase = z * 288;

    // ---- embed both inputs; fill sH (hi) + sL (lo), key-major ----
    {
        const float* src0 = x1 + (size_t)b * 4608;
        const float* src1 = x2 + (size_t)b * 4608;
        #pragma unroll
        for (int e = 0; e < 2; e++) {
            const float* src = (e == 0) ? src0 : src1;
            #pragma unroll
            for (int k = 0; k < 16; k++) {
                int g = t + k * 288;
                float v = src[g];
                int c   = g / 144;
                int rem = g - c * 144;
                int r   = rem / 12;
                int s   = rem - r * 12;
                int h = r / 3, p1 = r - h * 3;
                int w = s / 3, p2 = s - w * 3;
                int i = h * 4 + w;
                int j = (p1 * 3 + p2) * 32 + c + e * 288;
                float hv = trunc_tf32(v);
                sH[j * WSC + i] = hv;
                sL[j * WSC + i] = v - hv;
            }
        }
    }
    __syncthreads();

    const bool x3q  = (z == 1);
    const float bias0 = x3q ? LOG2_07 : LOG2_03;   // keys 0..287 (e1)
    const float bias1 = x3q ? LOG2_03 : LOG2_07;   // keys 288..575 (e2)

    // A1 fragments for 2 m-tiles (32 queries), hi & lo, loaded once
    uint32_t aH[2][2][4], aL[2][2][4];
    #pragma unroll
    for (int mh = 0; mh < 2; mh++) {
        #pragma unroll
        for (int ks = 0; ks < 2; ks++) {
            int r0 = (zbase + wid * 32 + mh * 16 + grp) * WSC + ks * 8 + tig;
            int r1 = r0 + 8 * WSC;
            aH[mh][ks][0] = fu(sH[r0]);     aH[mh][ks][1] = fu(sH[r1]);
            aH[mh][ks][2] = fu(sH[r0 + 4]); aH[mh][ks][3] = fu(sH[r1 + 4]);
            aL[mh][ks][0] = fu(sL[r0]);     aL[mh][ks][1] = fu(sL[r1]);
            aL[mh][ks][2] = fu(sL[r0 + 4]); aL[mh][ks][3] = fu(sL[r1 + 4]);
        }
    }

    float o[2][2][4];                 // [mh][dim-half][frag]
    #pragma unroll
    for (int mh = 0; mh < 2; mh++)
        #pragma unroll
        for (int d = 0; d < 2; d++)
            #pragma unroll
            for (int u = 0; u < 4; u++) o[mh][d][u] = 0.f;
    float zac[2][4] = {{0.f,0.f,0.f,0.f},{0.f,0.f,0.f,0.f}};  // [mh][seg*2+rowhalf]

    #pragma unroll 1
    for (int kt = 0; kt < 18; kt++) {
        const int pbase = kt * 32;
        const float bias = (kt < 9) ? bias0 : bias1;
        const int zi = (kt < 9) ? 0 : 2;

        #pragma unroll
        for (int nb = 0; nb < 4; nb++) {
            const int kb = pbase + nb * 8;
            // MMA1 B frag: n = key (row kb+grp), k = dim (tig / tig+4 / +8 / +12)
            int rb = (kb + grp) * WSC + tig;
            uint32_t bh00 = fu(sH[rb]),      bh01 = fu(sH[rb + 4]);
            uint32_t bh10 = fu(sH[rb + 8]),  bh11 = fu(sH[rb + 12]);
            uint32_t bl00 = fu(sL[rb]),      bl01 = fu(sL[rb + 4]);
            uint32_t bl10 = fu(sL[rb + 8]),  bl11 = fu(sL[rb + 12]);

            // MMA2 B frag (sigma key order): kpos tig -> key 2tig, kpos tig+4 -> 2tig+1
            int rk0 = (kb + 2 * tig) * WSC;
            int rk1 = rk0 + WSC;
            uint32_t kb0 = fu(sH[rk0 + grp]),     kb1 = fu(sH[rk1 + grp]);      // dims 0..7
            uint32_t kc0 = fu(sH[rk0 + grp + 8]), kc1 = fu(sH[rk1 + grp + 8]);  // dims 8..15

            #pragma unroll
            for (int mh = 0; mh < 2; mh++) {
                // two independent 3-deep chains (halved serial MMA latency)
                float ca[4] = {0.f, 0.f, 0.f, 0.f};
                float cb[4] = {0.f, 0.f, 0.f, 0.f};
                mma_tf32(ca, aH[mh][0], bh00, bh01);
                mma_tf32(cb, aH[mh][1], bh10, bh11);
                mma_tf32(ca, aH[mh][0], bl00, bl01);
                mma_tf32(cb, aH[mh][1], bl10, bl11);
                mma_tf32(ca, aL[mh][0], bh00, bh01);
                mma_tf32(cb, aL[mh][1], bh10, bh11);

                // w-fragment: rows {grp, grp+8}, keys {2tig, 2tig+1}
                float w0 = trunc_tf32(ex2a(fmaf(ca[0] + cb[0], LOG2E, bias)));
                float w1 = trunc_tf32(ex2a(fmaf(ca[1] + cb[1], LOG2E, bias)));
                float w2 = trunc_tf32(ex2a(fmaf(ca[2] + cb[2], LOG2E, bias)));
                float w3 = trunc_tf32(ex2a(fmaf(ca[3] + cb[3], LOG2E, bias)));
                zac[mh][zi]     += w0 + w1;
                zac[mh][zi + 1] += w2 + w3;

                // MMA2 A frag under sigma = {w0, w2, w1, w3} -- zero-copy relay
                uint32_t a2[4] = { fu(w0), fu(w2), fu(w1), fu(w3) };
                mma_tf32(o[mh][0], a2, kb0, kb1);
                mma_tf32(o[mh][1], a2, kc0, kc1);
            }
        }
    }

    // ---- Z: quad-reduce (lanes of same grp hold same rows) ----
    #pragma unroll
    for (int mh = 0; mh < 2; mh++)
        #pragma unroll
        for (int i2 = 0; i2 < 4; i2++) {
            zac[mh][i2] += __shfl_xor_sync(0xffffffffu, zac[mh][i2], 1);
            zac[mh][i2] += __shfl_xor_sync(0xffffffffu, zac[mh][i2], 2);
        }
    const float il0 = x3q ? (1.f / 0.7f) : (1.f / 0.3f);
    const float il1 = x3q ? (1.f / 0.3f) : (1.f / 0.7f);

    __syncthreads();            // all warps done with sL
    float* sO = sL;             // [288 local queries][WSC]
    #pragma unroll
    for (int mh = 0; mh < 2; mh++) {
        const float ivg  = 1.f / (zac[mh][0] * il0 + zac[mh][2] * il1);
        const float ivg8 = 1.f / (zac[mh][1] * il0 + zac[mh][3] * il1);
        int ro = (wid * 32 + mh * 16 + grp) * WSC + 2 * tig;
        sO[ro]     = o[mh][0][0] * ivg;   sO[ro + 1] = o[mh][0][1] * ivg;
        sO[ro + 8] = o[mh][1][0] * ivg;   sO[ro + 9] = o[mh][1][1] * ivg;
        int r8 = ro + 8 * WSC;
        sO[r8]     = o[mh][0][2] * ivg8;  sO[r8 + 1] = o[mh][0][3] * ivg8;
        sO[r8 + 8] = o[mh][1][2] * ivg8;  sO[r8 + 9] = o[mh][1][3] * ivg8;
    }
    __syncthreads();

    // ---- coalesced un-patch store; CTA owns exactly one output half ----
    float* dst = out + ((size_t)((z == 1) ? 0 : 1) * 512 + (size_t)b) * 4608;
    #pragma unroll
    for (int k = 0; k < 16; k++) {
        int g = t + k * 288;
        int c   = g / 144;
        int rem = g - c * 144;
        int r   = rem / 12;
        int s   = rem - r * 12;
        int h = r / 3, p1 = r - h * 3;
        int w = s / 3, p2 = s - w * 3;
        int i  = h * 4 + w;
        int tt = (p1 * 3 + p2) * 32 + c;   // local query col 0..287
        dst[g] = sO[tt * WSC + i];
    }
}

extern "C" void kernel_launch(void* const* d_in, const int* in_sizes, int n_in,
                              void* d_out, int out_size)
{
    const float* x1 = (const float*)d_in[0];
    const float* x2 = (const float*)d_in[1];
    float* out = (float*)d_out;
    const int smem_bytes = 2 * 11520 * sizeof(float);   // 92160
    cudaFuncSetAttribute(mixca_mma4, cudaFuncAttributeMaxDynamicSharedMemorySize,
                         smem_bytes);
    dim3 grid(512, 2);
    mixca_mma4<<<grid, 288, smem_bytes>>>(x1, x2, out);
}